// round 12
// baseline (speedup 1.0000x reference)
#include <cuda_runtime.h>
#include <cuda_fp16.h>
#include <math.h>
#include <stdint.h>

#define B_   4
#define S_   2048
#define HID_ 1024
#define NH_  4
#define D_   256
#define IM_  2048
#define E_   4
#define T_   (B_*S_)   // 8192 tokens
#define K3_  (3*HID_)  // 3072

// ---------------- scratch ----------------
__device__ float g_scores[(size_t)B_*NH_*S_*S_];            // 256 MB (f32 scores)
__device__ float g_h1[(size_t)T_*HID_];
__device__ float g_x2[(size_t)T_*HID_];
__device__ float g_rw[(size_t)T_*E_];
__device__ float g_red[S_];
__device__ float g_dpart[(size_t)E_*T_*HID_];               // 128 MB per-expert down partials
// half operands
__device__ __align__(16) __half g_probs[(size_t)B_*NH_*S_*S_];  // 128 MB
__device__ __align__(16) __half g_xn3[(size_t)T_*K3_];      // [xnh|xnh|xnl]
__device__ __align__(16) __half g_x2h[(size_t)T_*HID_];
__device__ __align__(16) __half g_qk3[(size_t)2*T_*K3_];    // q3 | k3 (per-head 768 concat)
__device__ __align__(16) __half g_vh[(size_t)T_*HID_];
__device__ __align__(16) __half g_vth[(size_t)B_*NH_*D_*S_];
__device__ __align__(16) __half g_oh[(size_t)T_*HID_];
__device__ __align__(16) __half g_gbh[(size_t)E_*T_*IM_];   // 128 MB
__device__ __align__(16) __half g_ubh[(size_t)E_*T_*IM_];   // 128 MB
// transposed half weights
__device__ __align__(16) __half g_w3qk[(size_t)2*HID_*K3_]; // [wqh|wql|wqh] | [wkh|wkl|wkh]
__device__ __align__(16) __half g_wvT[(size_t)HID_*HID_];
__device__ __align__(16) __half g_woT[(size_t)HID_*HID_];
__device__ __align__(16) __half g_gT[(size_t)E_*IM_*HID_];
__device__ __align__(16) __half g_uT[(size_t)E_*IM_*HID_];
__device__ __align__(16) __half g_dT[(size_t)E_*HID_*IM_];

// ---------------- helpers ----------------
__device__ __forceinline__ void cp16(void* dst, const void* src) {
    uint32_t d = (uint32_t)__cvta_generic_to_shared(dst);
    asm volatile("cp.async.cg.shared.global [%0], [%1], 16;" :: "r"(d), "l"(src));
}
#define CP_COMMIT() asm volatile("cp.async.commit_group;" ::: "memory")
template<int N> __device__ __forceinline__ void cp_wait() {
    asm volatile("cp.async.wait_group %0;" :: "n"(N) : "memory");
}
__device__ __forceinline__ void mma_f16(float* c, const unsigned* a, const unsigned* b) {
    asm volatile("mma.sync.aligned.m16n8k16.row.col.f32.f16.f16.f32 "
                 "{%0,%1,%2,%3},{%4,%5,%6,%7},{%8,%9},{%0,%1,%2,%3};"
                 : "+f"(c[0]), "+f"(c[1]), "+f"(c[2]), "+f"(c[3])
                 : "r"(a[0]), "r"(a[1]), "r"(a[2]), "r"(a[3]),
                   "r"(b[0]), "r"(b[1]));
}

__device__ __forceinline__ float blk_sum(float v) {
    __shared__ float sm[32];
    __syncthreads();
    int lane = threadIdx.x & 31, w = threadIdx.x >> 5;
    #pragma unroll
    for (int o = 16; o; o >>= 1) v += __shfl_down_sync(0xffffffffu, v, o);
    if (lane == 0) sm[w] = v;
    __syncthreads();
    int nw = blockDim.x >> 5;
    if (w == 0) {
        v = (lane < nw) ? sm[lane] : 0.f;
        #pragma unroll
        for (int o = 16; o; o >>= 1) v += __shfl_down_sync(0xffffffffu, v, o);
        if (lane == 0) sm[0] = v;
    }
    __syncthreads();
    return sm[0];
}
__device__ __forceinline__ float blk_max(float v) {
    __shared__ float sm[32];
    __syncthreads();
    int lane = threadIdx.x & 31, w = threadIdx.x >> 5;
    #pragma unroll
    for (int o = 16; o; o >>= 1) v = fmaxf(v, __shfl_down_sync(0xffffffffu, v, o));
    if (lane == 0) sm[w] = v;
    __syncthreads();
    int nw = blockDim.x >> 5;
    if (w == 0) {
        v = (lane < nw) ? sm[lane] : -INFINITY;
        #pragma unroll
        for (int o = 16; o; o >>= 1) v = fmaxf(v, __shfl_down_sync(0xffffffffu, v, o));
        if (lane == 0) sm[0] = v;
    }
    __syncthreads();
    return sm[0];
}

// ---------------- rmsnorm ----------------
// out3 (optional): [xh | xh | xl] concat, width 3*HID
// outf/outh (optional): f32 / plain half
__global__ void rmsnorm_kernel(const float* __restrict__ x, const float* __restrict__ w,
                               float* __restrict__ outf,
                               __half* __restrict__ outh,
                               __half* __restrict__ out3) {
    size_t t = blockIdx.x;
    float4 v = ((const float4*)(x + t * HID_))[threadIdx.x];
    float s = v.x*v.x + v.y*v.y + v.z*v.z + v.w*v.w;
    s = blk_sum(s);
    float r = rsqrtf(s * (1.f / HID_) + 1e-6f);
    float4 wv = ((const float4*)w)[threadIdx.x];
    float4 o;
    o.x = v.x * wv.x * r; o.y = v.y * wv.y * r;
    o.z = v.z * wv.z * r; o.w = v.w * wv.w * r;
    if (outf) ((float4*)(outf + t * HID_))[threadIdx.x] = o;
    __half2 h01 = __floats2half2_rn(o.x, o.y);
    __half2 h23 = __floats2half2_rn(o.z, o.w);
    if (outh) {
        ((__half2*)(outh + t * HID_))[2 * threadIdx.x + 0] = h01;
        ((__half2*)(outh + t * HID_))[2 * threadIdx.x + 1] = h23;
    }
    if (out3) {
        __half2 l01 = __floats2half2_rn(o.x - __low2float(h01), o.y - __high2float(h01));
        __half2 l23 = __floats2half2_rn(o.z - __low2float(h23), o.w - __high2float(h23));
        __half2* p = (__half2*)(out3 + t * K3_);
        int c = 2 * threadIdx.x;             // half2 index within 1024-wide slice (512 half2)
        p[c + 0] = h01;          p[c + 1] = h23;            // slice 0: hi
        p[c + 512 + 0] = h01;    p[c + 512 + 1] = h23;      // slice 1: hi
        p[c + 1024 + 0] = l01;   p[c + 1024 + 1] = l23;     // slice 2: lo
    }
}

// ---------------- weight transpose f32[R,C] -> half[C,R] ----------------
template<bool SPL>
__global__ void trw_kernel(__half* __restrict__ oh, __half* __restrict__ ol,
                           const float* __restrict__ in, int R, int C) {
    __shared__ float tile[32][33];
    long zo = (long)blockIdx.z * R * C;
    in += zo; oh += zo; if (SPL) ol += zo;
    int c0 = blockIdx.x * 32, r0 = blockIdx.y * 32;
    int x = threadIdx.x, y = threadIdx.y;
    #pragma unroll
    for (int i = 0; i < 32; i += 8)
        tile[y + i][x] = in[(long)(r0 + y + i) * C + c0 + x];
    __syncthreads();
    #pragma unroll
    for (int i = 0; i < 32; i += 8) {
        float f = tile[x][y + i];
        __half h = __float2half_rn(f);
        long idx = (long)(c0 + y + i) * R + r0 + x;
        oh[idx] = h;
        if (SPL) ol[idx] = __float2half_rn(f - __half2float(h));
    }
}

// ---------------- weight transpose -> 3-slice concat [wh | wl | wh], pitch 3*HID ----------------
__global__ void trw3_kernel(__half* __restrict__ o3, const float* __restrict__ in, int R, int C) {
    __shared__ float tile[32][33];
    int c0 = blockIdx.x * 32, r0 = blockIdx.y * 32;
    int x = threadIdx.x, y = threadIdx.y;
    #pragma unroll
    for (int i = 0; i < 32; i += 8)
        tile[y + i][x] = in[(long)(r0 + y + i) * C + c0 + x];
    __syncthreads();
    #pragma unroll
    for (int i = 0; i < 32; i += 8) {
        float f = tile[x][y + i];
        __half h = __float2half_rn(f);
        __half l = __float2half_rn(f - __half2float(h));
        long base = (long)(c0 + y + i) * K3_ + r0 + x;   // row = output n, col = k
        o3[base + 0]        = h;   // slice 0: hi
        o3[base + HID_]     = l;   // slice 1: lo
        o3[base + 2 * HID_] = h;   // slice 2: hi
    }
}

// ---------------- v transpose ----------------
__global__ void trv_kernel(__half* __restrict__ out, const __half* __restrict__ in) {
    __shared__ __half tile[32][33];
    int z = blockIdx.z, zb = z >> 2, zh = z & 3;
    const __half* ip = in + (long)zb * S_ * HID_ + (long)zh * D_;
    __half* op = out + (long)z * D_ * S_;
    int c0 = blockIdx.x * 32, r0 = blockIdx.y * 32;
    int x = threadIdx.x, y = threadIdx.y;
    #pragma unroll
    for (int i = 0; i < 32; i += 8)
        tile[y + i][x] = ip[(long)(r0 + y + i) * HID_ + c0 + x];
    __syncthreads();
    #pragma unroll
    for (int i = 0; i < 32; i += 8)
        op[(long)(c0 + y + i) * S_ + r0 + x] = tile[x][y + i];
}

// ================= half NT GEMM with cp.async (m16n8k16), 128x128, TBK=64 =================
// C = A[M,K] * B[N,K]^T, batched over blockIdx.z ((b,h) split, or expert = zh).
// EPI: 0 f32 store | 2 f32 C=v+auxf | 3 silu->half | 4 v*auxh->half | 7 half store
//      8 f32 C = v*rs[m*rsStride+zh] | 9 elu+1 -> qk3 3-slice concat (zh: 0=Q [h,h,l], 1=K [h,l,h])
#define TBK 64
#define PITCH 72
#define SZT (128 * PITCH * 2)     // 18432 B per tile
#define SEGS (TBK / 8)

template<int EPI>
__global__ __launch_bounds__(256, 2)
void hgemm(int M, int N, int K,
           const __half* __restrict__ Ahg, int lda, long sAb, long sAh,
           const __half* __restrict__ Bhg, int ldb, long sBb, long sBh,
           void* __restrict__ Cv, int ldc, long sCb, long sCh,
           void* __restrict__ aux,
           const float* __restrict__ rs, int rsStride) {
    constexpr int STAGE = 2 * SZT;

    int z  = blockIdx.z;
    int zb = z >> 2, zh = z & 3;
    Ahg += (long)zb * sAb + (long)zh * sAh;
    Bhg += (long)zb * sBb + (long)zh * sBh;
    long coff = (long)zb * sCb + (long)zh * sCh;

    extern __shared__ char smem[];

    int tid  = threadIdx.x;
    int lane = tid & 31;
    int warp = tid >> 5;
    int wm = (warp >> 2) * 64;
    int wn = (warp & 3) * 32;
    int g = lane >> 2;
    int t = lane & 3;

    int blockRow = blockIdx.y * 128;
    int blockCol = blockIdx.x * 128;
    const __half* Ab = Ahg + (long)blockRow * lda;
    const __half* Bb = Bhg + (long)blockCol * ldb;

    int nIter = K / TBK;

    auto issue = [&](int st, int kt) {
        if (kt < nIter) {
            long k0 = (long)kt * TBK;
            char* sb = smem + st * STAGE;
            __half* As = (__half*)sb;
            __half* Bs = (__half*)(sb + SZT);
            #pragma unroll
            for (int c = 0; c < SEGS / 2; c++) {
                int idx = tid + c * 256;
                int row = idx / SEGS;
                int seg = (idx % SEGS) * 8;
                cp16(&As[row * PITCH + seg], Ab + (long)row * lda + k0 + seg);
                cp16(&Bs[row * PITCH + seg], Bb + (long)row * ldb + k0 + seg);
            }
        }
        CP_COMMIT();
    };

    float acc[4][4][4] = {};

    issue(0, 0);
    issue(1, 1);
    for (int kt = 0; kt < nIter; kt++) {
        int st = kt & 1;
        cp_wait<1>();
        __syncthreads();
        char* sb = smem + st * STAGE;
        const __half* As = (const __half*)sb;
        const __half* Bs = (const __half*)(sb + SZT);

        #pragma unroll
        for (int ks = 0; ks < TBK; ks += 16) {
            unsigned a[4][4], b[4][2];
            #pragma unroll
            for (int mi = 0; mi < 4; mi++) {
                const __half* base = As + (wm + mi * 16 + g) * PITCH + ks + 2 * t;
                a[mi][0] = *(const unsigned*)(base);
                a[mi][1] = *(const unsigned*)(base + 8 * PITCH);
                a[mi][2] = *(const unsigned*)(base + 8);
                a[mi][3] = *(const unsigned*)(base + 8 * PITCH + 8);
            }
            #pragma unroll
            for (int ni = 0; ni < 4; ni++) {
                const __half* base = Bs + (wn + ni * 8 + g) * PITCH + ks + 2 * t;
                b[ni][0] = *(const unsigned*)(base);
                b[ni][1] = *(const unsigned*)(base + 8);
            }
            #pragma unroll
            for (int mi = 0; mi < 4; mi++)
                #pragma unroll
                for (int ni = 0; ni < 4; ni++)
                    mma_f16(acc[mi][ni], a[mi], b[ni]);
        }
        __syncthreads();
        issue(st, kt + 2);
    }

    // ---- epilogue ----
    float* Cf = (float*)Cv + coff;
    __half* Ch = (__half*)Cv + coff;
    const float* auxf = (const float*)aux ? (const float*)aux + coff : nullptr;
    const __half* auxh = (const __half*)aux ? (const __half*)aux + coff : nullptr;

    #pragma unroll
    for (int mi = 0; mi < 4; mi++) {
        int r0 = blockRow + wm + mi * 16 + g;
        int r1 = r0 + 8;
        float sc0 = 0.f, sc1 = 0.f;
        if (EPI == 8) {
            sc0 = rs[(long)r0 * rsStride + zh];
            sc1 = rs[(long)r1 * rsStride + zh];
        }
        #pragma unroll
        for (int ni = 0; ni < 4; ni++) {
            int col = blockCol + wn + ni * 8 + 2 * t;
            long i0 = (long)r0 * ldc + col;
            long i1 = (long)r1 * ldc + col;
            float v0 = acc[mi][ni][0], v1 = acc[mi][ni][1];
            float v2 = acc[mi][ni][2], v3 = acc[mi][ni][3];
            if (EPI == 0) {
                *(float2*)(Cf + i0) = make_float2(v0, v1);
                *(float2*)(Cf + i1) = make_float2(v2, v3);
            } else if (EPI == 2) {
                float2 x0 = *(const float2*)(auxf + i0);
                float2 x1 = *(const float2*)(auxf + i1);
                *(float2*)(Cf + i0) = make_float2(v0 + x0.x, v1 + x0.y);
                *(float2*)(Cf + i1) = make_float2(v2 + x1.x, v3 + x1.y);
            } else if (EPI == 3) {
                *(__half2*)(Ch + i0) = __floats2half2_rn(v0 / (1.f + expf(-v0)), v1 / (1.f + expf(-v1)));
                *(__half2*)(Ch + i1) = __floats2half2_rn(v2 / (1.f + expf(-v2)), v3 / (1.f + expf(-v3)));
            } else if (EPI == 4) {
                __half2 g0 = *(const __half2*)(auxh + i0);
                __half2 g1 = *(const __half2*)(auxh + i1);
                *(__half2*)(Ch + i0) = __floats2half2_rn(v0 * __low2float(g0), v1 * __high2float(g0));
                *(__half2*)(Ch + i1) = __floats2half2_rn(v2 * __low2float(g1), v3 * __high2float(g1));
            } else if (EPI == 8) {
                *(float2*)(Cf + i0) = make_float2(v0 * sc0, v1 * sc0);
                *(float2*)(Cf + i1) = make_float2(v2 * sc1, v3 * sc1);
            } else if (EPI == 9) {
                // elu+1 -> 3-slice per-head concat (width K3_, head block 768)
                float e0 = (v0 > 0.f) ? v0 + 1.f : expf(v0);
                float e1 = (v1 > 0.f) ? v1 + 1.f : expf(v1);
                float e2 = (v2 > 0.f) ? v2 + 1.f : expf(v2);
                float e3 = (v3 > 0.f) ? v3 + 1.f : expf(v3);
                __half2 h0 = __floats2half2_rn(e0, e1);
                __half2 h1v = __floats2half2_rn(e2, e3);
                __half2 l0 = __floats2half2_rn(e0 - __low2float(h0), e1 - __high2float(h0));
                __half2 l1 = __floats2half2_rn(e2 - __low2float(h1v), e3 - __high2float(h1v));
                int head = col >> 8, cn = col & 255;
                long b0 = (long)r0 * K3_ + 768 * head + cn;
                long b1 = (long)r1 * K3_ + 768 * head + cn;
                if (zh == 0) {  // Q: [h, h, l]
                    *(__half2*)(Ch + b0) = h0;        *(__half2*)(Ch + b1) = h1v;
                    *(__half2*)(Ch + b0 + 256) = h0;  *(__half2*)(Ch + b1 + 256) = h1v;
                    *(__half2*)(Ch + b0 + 512) = l0;  *(__half2*)(Ch + b1 + 512) = l1;
                } else {        // K: [h, l, h]
                    *(__half2*)(Ch + b0) = h0;        *(__half2*)(Ch + b1) = h1v;
                    *(__half2*)(Ch + b0 + 256) = l0;  *(__half2*)(Ch + b1 + 256) = l1;
                    *(__half2*)(Ch + b0 + 512) = h0;  *(__half2*)(Ch + b1 + 512) = h1v;
                }
            } else { // 7
                *(__half2*)(Ch + i0) = __floats2half2_rn(v0, v1);
                *(__half2*)(Ch + i1) = __floats2half2_rn(v2, v3);
            }
        }
    }
}

#define SMEM_NS (2 * 2 * SZT)   // 73728, occ 2

// ---------------- MoE reduce ----------------
__global__ void moe_reduce_kernel(float* __restrict__ out, const float* __restrict__ h1,
                                  const float* __restrict__ dp) {
    size_t i = (size_t)blockIdx.x * 256 + threadIdx.x;
    const size_t n = (size_t)T_ * HID_;
    float4 r = ((const float4*)h1)[i];
    #pragma unroll
    for (int e = 0; e < E_; e++) {
        float4 p = ((const float4*)(dp + e * n))[i];
        r.x += p.x; r.y += p.y; r.z += p.z; r.w += p.w;
    }
    ((float4*)out)[i] = r;
}

// ---------------- softmax: f32 scores -> half probs ----------------
__global__ void softmax_kernel(const float* __restrict__ x, __half* __restrict__ pr) {
    size_t row = blockIdx.x;
    const float4* p = (const float4*)(x + row * (size_t)S_);
    float4 a = p[threadIdx.x];
    float4 b = p[threadIdx.x + 256];
    float mx = fmaxf(fmaxf(fmaxf(a.x, a.y), fmaxf(a.z, a.w)),
                     fmaxf(fmaxf(b.x, b.y), fmaxf(b.z, b.w)));
    mx = blk_max(mx);
    a.x = expf(a.x - mx); a.y = expf(a.y - mx); a.z = expf(a.z - mx); a.w = expf(a.w - mx);
    b.x = expf(b.x - mx); b.y = expf(b.y - mx); b.z = expf(b.z - mx); b.w = expf(b.w - mx);
    float s = a.x + a.y + a.z + a.w + b.x + b.y + b.z + b.w;
    s = blk_sum(s);
    float inv = 1.f / s;
    __half2* o = (__half2*)(pr + row * (size_t)S_);
    o[2 * threadIdx.x + 0]   = __floats2half2_rn(a.x * inv, a.y * inv);
    o[2 * threadIdx.x + 1]   = __floats2half2_rn(a.z * inv, a.w * inv);
    o[2 * (threadIdx.x + 256) + 0] = __floats2half2_rn(b.x * inv, b.y * inv);
    o[2 * (threadIdx.x + 256) + 1] = __floats2half2_rn(b.z * inv, b.w * inv);
}

// ---------------- router ----------------
__global__ void router_kernel(const float* __restrict__ x2,
                              const float* __restrict__ rwW,
                              const float* __restrict__ rb,
                              float* __restrict__ rwOut) {
    size_t t = blockIdx.x;
    const float* x = x2 + t * HID_;
    float s0 = 0, s1 = 0, s2 = 0, s3 = 0;
    for (int j = threadIdx.x; j < HID_; j += 256) {
        float xv = x[j];
        float4 w = ((const float4*)rwW)[j];
        s0 = fmaf(xv, w.x, s0); s1 = fmaf(xv, w.y, s1);
        s2 = fmaf(xv, w.z, s2); s3 = fmaf(xv, w.w, s3);
    }
    __shared__ float sm[8][4];
    int lane = threadIdx.x & 31, w = threadIdx.x >> 5;
    #pragma unroll
    for (int o = 16; o; o >>= 1) {
        s0 += __shfl_down_sync(0xffffffffu, s0, o);
        s1 += __shfl_down_sync(0xffffffffu, s1, o);
        s2 += __shfl_down_sync(0xffffffffu, s2, o);
        s3 += __shfl_down_sync(0xffffffffu, s3, o);
    }
    if (lane == 0) { sm[w][0] = s0; sm[w][1] = s1; sm[w][2] = s2; sm[w][3] = s3; }
    __syncthreads();
    if (threadIdx.x == 0) {
        float l[4];
        #pragma unroll
        for (int e = 0; e < 4; e++) {
            float v = 0;
            #pragma unroll
            for (int ww = 0; ww < 8; ww++) v += sm[ww][e];
            l[e] = v + rb[e];
        }
        float mx = fmaxf(fmaxf(l[0], l[1]), fmaxf(l[2], l[3]));
        float sum = 0;
        #pragma unroll
        for (int e = 0; e < 4; e++) { l[e] = expf(l[e] - mx); sum += l[e]; }
        float inv = 1.f / sum;
        #pragma unroll
        for (int e = 0; e < 4; e++) rwOut[t * E_ + e] = l[e] * inv;
    }
}

// ---------------- balance loss ----------------
__global__ void balance1_kernel(const float* __restrict__ rw, float* __restrict__ red) {
    int s = blockIdx.x;
    if (threadIdx.x < 4) {
        int e = threadIdx.x;
        float m = 0;
        #pragma unroll
        for (int b = 0; b < B_; b++) m += rw[((size_t)(b * S_ + s)) * E_ + e];
        m = m * (1.f / B_) - (1.f / E_);
        float v = m * m;
        v += __shfl_xor_sync(0xF, v, 1);
        v += __shfl_xor_sync(0xF, v, 2);
        if (e == 0) red[s] = v;
    }
}
__global__ void balance2_kernel(const float* __restrict__ red, float* __restrict__ out) {
    float v = red[threadIdx.x] + red[threadIdx.x + 1024];
    v = blk_sum(v);
    if (threadIdx.x == 0) out[0] = v / ((float)S_ * E_) * 0.01f;
}

// ---------------- driver ----------------
extern "C" void kernel_launch(void* const* d_in, const int* in_sizes, int n_in,
                              void* d_out, int out_size) {
    (void)in_sizes; (void)n_in;
    const float* hidden   = (const float*)d_in[0];
    const float* ln1_w    = (const float*)d_in[1];
    const float* wq       = (const float*)d_in[2];
    const float* wk       = (const float*)d_in[3];
    const float* wv       = (const float*)d_in[4];
    const float* wo       = (const float*)d_in[5];
    const float* ln2_w    = (const float*)d_in[6];
    const float* router_w = (const float*)d_in[7];
    const float* router_b = (const float*)d_in[8];
    const float* gate_w   = (const float*)d_in[9];
    const float* up_w     = (const float*)d_in[10];
    const float* down_w   = (const float*)d_in[11];
    float* out = (float*)d_out;

    float *sc, *h1, *x2, *rw, *red, *dp;
    __half *probs, *xn3, *x2h, *qk3, *vh, *vth, *oh, *gbh, *ubh;
    __half *w3qk, *wvT, *woT, *gT, *uT, *dT;
    cudaGetSymbolAddress((void**)&sc,  g_scores);
    cudaGetSymbolAddress((void**)&h1,  g_h1);
    cudaGetSymbolAddress((void**)&x2,  g_x2);
    cudaGetSymbolAddress((void**)&rw,  g_rw);
    cudaGetSymbolAddress((void**)&red, g_red);
    cudaGetSymbolAddress((void**)&dp,  g_dpart);
    cudaGetSymbolAddress((void**)&probs, g_probs);
    cudaGetSymbolAddress((void**)&xn3, g_xn3);
    cudaGetSymbolAddress((void**)&x2h, g_x2h);
    cudaGetSymbolAddress((void**)&qk3, g_qk3);
    cudaGetSymbolAddress((void**)&vh,  g_vh);
    cudaGetSymbolAddress((void**)&vth, g_vth);
    cudaGetSymbolAddress((void**)&oh,  g_oh);
    cudaGetSymbolAddress((void**)&gbh, g_gbh);
    cudaGetSymbolAddress((void**)&ubh, g_ubh);
    cudaGetSymbolAddress((void**)&w3qk, g_w3qk);
    cudaGetSymbolAddress((void**)&wvT, g_wvT);
    cudaGetSymbolAddress((void**)&woT, g_woT);
    cudaGetSymbolAddress((void**)&gT,  g_gT);
    cudaGetSymbolAddress((void**)&uT,  g_uT);
    cudaGetSymbolAddress((void**)&dT,  g_dT);

    cudaFuncSetAttribute(hgemm<0>, cudaFuncAttributeMaxDynamicSharedMemorySize, SMEM_NS);
    cudaFuncSetAttribute(hgemm<2>, cudaFuncAttributeMaxDynamicSharedMemorySize, SMEM_NS);
    cudaFuncSetAttribute(hgemm<3>, cudaFuncAttributeMaxDynamicSharedMemorySize, SMEM_NS);
    cudaFuncSetAttribute(hgemm<4>, cudaFuncAttributeMaxDynamicSharedMemorySize, SMEM_NS);
    cudaFuncSetAttribute(hgemm<7>, cudaFuncAttributeMaxDynamicSharedMemorySize, SMEM_NS);
    cudaFuncSetAttribute(hgemm<8>, cudaFuncAttributeMaxDynamicSharedMemorySize, SMEM_NS);
    cudaFuncSetAttribute(hgemm<9>, cudaFuncAttributeMaxDynamicSharedMemorySize, SMEM_NS);

    dim3 tb(32, 8);
    // weight converts/transposes
    trw3_kernel<<<dim3(32, 32, 1), tb>>>(w3qk, wq, HID_, HID_);
    trw3_kernel<<<dim3(32, 32, 1), tb>>>(w3qk + (size_t)HID_ * K3_, wk, HID_, HID_);
    trw_kernel<false><<<dim3(32, 32, 1), tb>>>(wvT, nullptr, wv, HID_, HID_);
    trw_kernel<false><<<dim3(32, 32, 1), tb>>>(woT, nullptr, wo, HID_, HID_);
    trw_kernel<false><<<dim3(64, 32, 4), tb>>>(gT, nullptr, gate_w, HID_, IM_);
    trw_kernel<false><<<dim3(64, 32, 4), tb>>>(uT, nullptr, up_w, HID_, IM_);
    trw_kernel<false><<<dim3(32, 64, 4), tb>>>(dT, nullptr, down_w, IM_, HID_);

    // 1) rmsnorm1 -> xn3 concat
    rmsnorm_kernel<<<T_, 256>>>(hidden, ln1_w, nullptr, nullptr, xn3);

    dim3 gproj(HID_ / 128, T_ / 128, 1);
    // 2) Q+K projection: ONE plain GEMM over K3 (z: 0=Q, 1=K), EPI 9 writes qk3 concat
    dim3 gqk(HID_ / 128, T_ / 128, 2);
    hgemm<9><<<gqk, 256, SMEM_NS>>>(T_, HID_, K3_,
                                    xn3, K3_, 0, 0,
                                    w3qk, K3_, 0, (long)HID_ * K3_,
                                    qk3, 0, 0, (long)T_ * K3_,
                                    nullptr, nullptr, 0);
    // V projection: A = xn3 slice 0 (hi), lda = K3
    hgemm<7><<<gproj, 256, SMEM_NS>>>(T_, HID_, HID_,
                                      xn3, K3_, 0, 0,
                                      wvT, HID_, 0, 0,
                                      vh, HID_, 0, 0, nullptr, nullptr, 0);
    // v transpose per head
    trv_kernel<<<dim3(D_ / 32, S_ / 32, B_ * NH_), tb>>>(vth, vh);

    // 3) scores: plain GEMM, K=768 per head over qk3 concat
    __half* q3 = qk3;
    __half* k3 = qk3 + (size_t)T_ * K3_;
    dim3 gsc(S_ / 128, S_ / 128, B_ * NH_);
    hgemm<0><<<gsc, 256, SMEM_NS>>>(S_, S_, 768,
                                    q3, K3_, (long)S_ * K3_, 768,
                                    k3, K3_, (long)S_ * K3_, 768,
                                    sc, S_, (long)NH_ * S_ * S_, (long)S_ * S_,
                                    nullptr, nullptr, 0);
    // 4) softmax -> half probs
    softmax_kernel<<<B_ * NH_ * S_, 256>>>(sc, probs);

    // 5) O = probs @ vth^T -> half oh
    dim3 gpv(D_ / 128, S_ / 128, B_ * NH_);
    hgemm<7><<<gpv, 256, SMEM_NS>>>(S_, D_, S_,
                                    probs, S_, (long)NH_ * S_ * S_, (long)S_ * S_,
                                    vth, S_, (long)NH_ * D_ * S_, (long)D_ * S_,
                                    oh, HID_, (long)S_ * HID_, (long)D_,
                                    nullptr, nullptr, 0);
    // 6) h1 = hidden + oh @ woT^T
    hgemm<2><<<gproj, 256, SMEM_NS>>>(T_, HID_, HID_, oh, HID_, 0, 0,
                                      woT, HID_, 0, 0, h1, HID_, 0, 0,
                                      (void*)hidden, nullptr, 0);
    // 7) rmsnorm2 -> f32 + half
    rmsnorm_kernel<<<T_, 256>>>(h1, ln2_w, x2, x2h, nullptr);
    // 8) router
    router_kernel<<<T_, 256>>>(x2, router_w, router_b, rw);
    // 9) balance loss
    if (out_size > T_ * HID_) {
        balance1_kernel<<<S_, 32>>>(rw, red);
        balance2_kernel<<<1, 1024>>>(red, out + (size_t)T_ * HID_);
    }

    // 10) MoE — expert-batched via blockIdx.z (zh = expert)
    dim3 gmoe(IM_ / 128, T_ / 128, E_);
    dim3 gdown(HID_ / 128, T_ / 128, E_);
    hgemm<3><<<gmoe, 256, SMEM_NS>>>(T_, IM_, HID_,
                                     x2h, HID_, 0, 0,
                                     gT, HID_, 0, (long)IM_ * HID_,
                                     gbh, IM_, 0, (long)T_ * IM_,
                                     nullptr, nullptr, 0);
    hgemm<4><<<gmoe, 256, SMEM_NS>>>(T_, IM_, HID_,
                                     x2h, HID_, 0, 0,
                                     uT, HID_, 0, (long)IM_ * HID_,
                                     ubh, IM_, 0, (long)T_ * IM_,
                                     gbh, nullptr, 0);
    hgemm<8><<<gdown, 256, SMEM_NS>>>(T_, HID_, IM_,
                                      ubh, IM_, 0, (long)T_ * IM_,
                                      dT, IM_, 0, (long)HID_ * IM_,
                                      dp, HID_, 0, (long)T_ * HID_,
                                      nullptr, rw, E_);
    // reduce: out = h1 + sum_e dpart[e]
    moe_reduce_kernel<<<(T_ * HID_ / 4) / 256, 256>>>(out, h1, dp);
}